// round 1
// baseline (speedup 1.0000x reference)
#include <cuda_runtime.h>
#include <math.h>

#define Bdim 4
#define Nseq 2048
#define Ddim 1024
#define Hh   8
#define HDd  64
#define FFd  4096
#define Ttok 8192                 // B*N
#define ETA_C 0.1f
#define DT_C  0.01f

// ---------------- scratch (static device globals; no allocations) ----------------
__device__ float g_V[Ttok];
__device__ float g_gamma[Ttok];
__device__ float g_a[Ttok * 2];
__device__ float g_bcf[Ttok * 2];
__device__ float g_x1[(size_t)Ttok * Ddim];
__device__ float g_xn2[(size_t)Ttok * Ddim];
__device__ float g_qkv[(size_t)Ttok * 1536];
__device__ float g_Qs[(size_t)Ttok * 512];
__device__ float g_Oin[(size_t)Ttok * 512];
__device__ float g_heb[(size_t)Ttok * 512];
__device__ float g_U[32 * 32 * 4096];       // [bh][chunk][d][e]
__device__ float g_Wst[32 * 32 * 4096];     // [bh][chunk][d][e]
__device__ float g_Pl[32 * 32];
__device__ float g_x2[(size_t)Ttok * Ddim];
__device__ float g_xn3[(size_t)Ttok * Ddim];
__device__ float g_ff[(size_t)Ttok * FFd];

// ---------------- helpers ----------------
__device__ __forceinline__ float blk_sum256(float v, float* sh) {
    int t = threadIdx.x;
#pragma unroll
    for (int o = 16; o > 0; o >>= 1) v += __shfl_down_sync(0xffffffffu, v, o);
    if ((t & 31) == 0) sh[t >> 5] = v;
    __syncthreads();
    if (t < 32) {
        float r = (t < 8) ? sh[t] : 0.f;
#pragma unroll
        for (int o = 4; o > 0; o >>= 1) r += __shfl_down_sync(0xffffffffu, r, o);
        if (t == 0) sh[0] = r;
    }
    __syncthreads();
    float r = sh[0];
    __syncthreads();
    return r;
}

__device__ __forceinline__ float gelu_f(float x) {
    float x3 = x * x * x;
    float u = 0.7978845608028654f * (x + 0.044715f * x3);
    return 0.5f * x * (1.f + tanhf(u));
}

// ---------------- K1: LN1 + potential projection ----------------
__global__ void ln1_pot_kernel(const float* __restrict__ x, const float* __restrict__ g1,
                               const float* __restrict__ b1, const float* __restrict__ wpot,
                               const float* __restrict__ bpot) {
    int row = blockIdx.x;
    int t = threadIdx.x;
    __shared__ float sh[8];
    const float4* xr = (const float4*)(x + (size_t)row * Ddim);
    float4 xv = xr[t];
    float s = xv.x + xv.y + xv.z + xv.w;
    float ss = xv.x * xv.x + xv.y * xv.y + xv.z * xv.z + xv.w * xv.w;
    s = blk_sum256(s, sh);
    ss = blk_sum256(ss, sh);
    float m = s * (1.f / Ddim);
    float var = ss * (1.f / Ddim) - m * m;
    float rstd = rsqrtf(var + 1e-5f);
    float xa[4] = {xv.x, xv.y, xv.z, xv.w};
    float p0 = 0.f, p1 = 0.f;
#pragma unroll
    for (int j = 0; j < 4; j++) {
        int col = t * 4 + j;
        float xn = (xa[j] - m) * rstd * g1[col] + b1[col];
        p0 += xn * wpot[col * 2];
        p1 += xn * wpot[col * 2 + 1];
    }
    p0 = blk_sum256(p0, sh);
    p1 = blk_sum256(p1, sh);
    if (t == 0) {
        g_V[row] = p0 + bpot[0];
        float z = p1 + bpot[1];
        float sp = (z > 20.f) ? z : log1pf(expf(z));
        g_gamma[row] = sp + 0.1f;
    }
}

// ---------------- K2: continued-fraction scans (fwd a, bwd b) ----------------
__global__ void bk_scan_kernel() {
    int bb = blockIdx.x >> 1;
    int dir = blockIdx.x & 1;
    __shared__ float dre[128], dii[128], ore[128], oim[128];
    int t = threadIdx.x;
    float pre = 0.f, pim = 0.f;
    float* out = dir ? g_bcf : g_a;
    for (int c = 0; c < 16; c++) {
        int j = c * 128 + t;
        int pos = dir ? (Nseq - 1 - j) : j;
        int gi = bb * Nseq + pos;
        dre[t] = g_V[gi] + 2.f;
        dii[t] = -g_gamma[gi];
        __syncthreads();
        if (t == 0) {
            for (int u = 0; u < 128; u++) {
                float ar, ai;
                if (c == 0 && u == 0) {
                    ar = dre[0]; ai = dii[0];
                } else {
                    float inv = 1.f / (pre * pre + pim * pim);
                    ar = dre[u] - pre * inv;   // d - Re(1/prev)
                    ai = dii[u] + pim * inv;   // d - Im(1/prev) ; Im(1/z) = -im/|z|^2
                }
                ore[u] = ar; oim[u] = ai;
                pre = ar; pim = ai;
            }
        }
        __syncthreads();
        out[gi * 2] = ore[t];
        out[gi * 2 + 1] = oim[t];
        __syncthreads();
    }
}

// ---------------- K3: BK combine + residual + LN2 ----------------
__global__ void bk_res_ln2_kernel(const float* __restrict__ x, const float* __restrict__ wbk,
                                  const float* __restrict__ bbk, const float* __restrict__ g2,
                                  const float* __restrict__ b2) {
    int row = blockIdx.x;
    int t = threadIdx.x;
    __shared__ float sh[8];
    __shared__ float f01[2];
    if (t == 0) {
        float are = g_a[row * 2], aim = g_a[row * 2 + 1];
        float bre = g_bcf[row * 2], bim = g_bcf[row * 2 + 1];
        float dr = g_V[row] + 2.f, di = -g_gamma[row];
        float nr = are + bre - dr, ni = aim + bim - di;
        float inv = 1.f / (nr * nr + ni * ni);
        f01[0] = nr * inv;
        f01[1] = -ni * inv;
    }
    __syncthreads();
    float f0 = f01[0], f1 = f01[1];
    size_t base = (size_t)row * Ddim;
    float y[4];
    float s = 0.f, ss = 0.f;
#pragma unroll
    for (int j = 0; j < 4; j++) {
        int col = t * 4 + j;
        float v = x[base + col] + f0 * wbk[col] + f1 * wbk[Ddim + col] + bbk[col];
        y[j] = v;
        s += v;
        ss += v * v;
        g_x1[base + col] = v;
    }
    s = blk_sum256(s, sh);
    ss = blk_sum256(ss, sh);
    float m = s * (1.f / Ddim);
    float var = ss * (1.f / Ddim) - m * m;
    float rstd = rsqrtf(var + 1e-5f);
#pragma unroll
    for (int j = 0; j < 4; j++) {
        int col = t * 4 + j;
        g_xn2[base + col] = (y[j] - m) * rstd * g2[col] + b2[col];
    }
}

// ---------------- LN3 ----------------
__global__ void ln3_kernel(const float* __restrict__ g3, const float* __restrict__ b3) {
    int row = blockIdx.x;
    int t = threadIdx.x;
    __shared__ float sh[8];
    size_t base = (size_t)row * Ddim;
    float4 xv = *(const float4*)&g_x2[base + t * 4];
    float s = xv.x + xv.y + xv.z + xv.w;
    float ss = xv.x * xv.x + xv.y * xv.y + xv.z * xv.z + xv.w * xv.w;
    s = blk_sum256(s, sh);
    ss = blk_sum256(ss, sh);
    float m = s * (1.f / Ddim);
    float var = ss * (1.f / Ddim) - m * m;
    float rstd = rsqrtf(var + 1e-5f);
    float xa[4] = {xv.x, xv.y, xv.z, xv.w};
#pragma unroll
    for (int j = 0; j < 4; j++) {
        int col = t * 4 + j;
        g_xn3[base + col] = (xa[j] - m) * rstd * g3[col] + b3[col];
    }
}

// ---------------- fp32 SIMT GEMM 128x128x8, 256 thr, 8x8 micro ----------------
// C[M,N] = A[M,K] @ B[K,N] + bias ; EPI==1 -> gelu ; Rd!=null -> += Rd
template <int EPI>
__global__ __launch_bounds__(256, 2) void sgemm_kernel(const float* __restrict__ A,
                                                       const float* __restrict__ B,
                                                       const float* __restrict__ bias,
                                                       const float* __restrict__ Rd,
                                                       float* __restrict__ C, int M, int N, int K) {
    __shared__ float As[8][128];
    __shared__ float Bs[8][128];
    int t = threadIdx.x;
    int m0 = blockIdx.y * 128, n0 = blockIdx.x * 128;
    int tx = t & 15, ty = t >> 4;
    int arow = t >> 1, acol = (t & 1) * 4;
    int brow = t >> 5, bcol = (t & 31) * 4;
    const float* Ap = A + (size_t)(m0 + arow) * K + acol;
    const float* Bp = B + (size_t)brow * N + n0 + bcol;
    float acc[8][8];
#pragma unroll
    for (int i = 0; i < 8; i++)
#pragma unroll
        for (int j = 0; j < 8; j++) acc[i][j] = 0.f;

    for (int k0 = 0; k0 < K; k0 += 8) {
        float4 av = *(const float4*)(Ap + k0);
        float4 bv = *(const float4*)(Bp + (size_t)k0 * N);
        __syncthreads();
        As[acol + 0][arow] = av.x;
        As[acol + 1][arow] = av.y;
        As[acol + 2][arow] = av.z;
        As[acol + 3][arow] = av.w;
        *(float4*)&Bs[brow][bcol] = bv;
        __syncthreads();
#pragma unroll
        for (int kk = 0; kk < 8; kk++) {
            float a[8], bb[8];
            *(float4*)(a) = *(const float4*)&As[kk][ty * 8];
            *(float4*)(a + 4) = *(const float4*)&As[kk][ty * 8 + 4];
            *(float4*)(bb) = *(const float4*)&Bs[kk][tx * 8];
            *(float4*)(bb + 4) = *(const float4*)&Bs[kk][tx * 8 + 4];
#pragma unroll
            for (int i = 0; i < 8; i++)
#pragma unroll
                for (int j = 0; j < 8; j++) acc[i][j] += a[i] * bb[j];
        }
    }
#pragma unroll
    for (int i = 0; i < 8; i++) {
        int row = m0 + ty * 8 + i;
        size_t off = (size_t)row * N + n0 + tx * 8;
#pragma unroll
        for (int j = 0; j < 8; j++) {
            float v = acc[i][j] + bias[n0 + tx * 8 + j];
            if (EPI == 1) v = gelu_f(v);
            if (Rd != nullptr) v += Rd[off + j];
            C[off + j] = v;
        }
    }
}

// ---------------- Hebbian chunked linear attention ----------------
// swizzled K tile index (bank-conflict-free for row-strided access)
__device__ __forceinline__ int ksw(int s, int d) {
    return s * 64 + (((((d >> 2) ^ (s & 15)) & 15) << 2) | (d & 3));
}
__device__ __forceinline__ int ksw4(int s, int d4) {
    return s * 64 + ((((d4 ^ (s & 15)) & 15) << 2));
}

// H1: per (b,h,chunk): P-scan, Qs/Ks, S (masked), O_intra = S V, U = Ks^T V
__global__ __launch_bounds__(256) void heb_intra_kernel() {
    int bid = blockIdx.x;          // ((b*8+h)*32 + c)
    int c = bid & 31;
    int bh = bid >> 5;
    int h = bh & 7;
    int b = bh >> 3;
    int t0 = b * Nseq + c * 64;
    __shared__ float shQ[4096];    // Q (scaled), later V
    __shared__ float shK[4096];    // Ks, swizzled
    __shared__ float shS[4096];    // P/Pinv during load, then S
    int t = threadIdx.x;

    // gamma -> P (inclusive decay product) in shS[0..63]
    if (t < 64) shS[t] = g_gamma[t0 + t];
    __syncthreads();
    if (t == 0) {
        float cum = 0.f;
        for (int i = 0; i < 64; i++) {
            cum += shS[i];
            shS[i] = expf(-DT_C * cum);
        }
        g_Pl[bh * 32 + c] = shS[63];
    }
    __syncthreads();
    if (t < 64) shS[64 + t] = 1.f / shS[t];
    __syncthreads();

    // load Q (scaled by P) and K (scaled by 1/P, swizzled); also emit Qs to global
    for (int idx = t; idx < 4096; idx += 256) {
        int i = idx >> 6, d = idx & 63;
        size_t qb = (size_t)(t0 + i) * 1536 + h * 64 + d;
        float qs = g_qkv[qb] * shS[i];
        shQ[i * 64 + d] = qs;
        g_Qs[(size_t)(t0 + i) * 512 + h * 64 + d] = qs;
        shK[ksw(i, d)] = g_qkv[qb + 512] * shS[64 + i];
    }
    __syncthreads();

    // S[i][s] = eta * Qs_i . Ks_s  (masked s<=i), 4x4 micro tiles
    {
        int i0 = (t >> 4) * 4, s0 = (t & 15) * 4;
        float accS[4][4];
#pragma unroll
        for (int r = 0; r < 4; r++)
#pragma unroll
            for (int q = 0; q < 4; q++) accS[r][q] = 0.f;
#pragma unroll
        for (int d4 = 0; d4 < 16; d4++) {
            float4 qa[4], ka[4];
#pragma unroll
            for (int r = 0; r < 4; r++) {
                qa[r] = *(const float4*)&shQ[(i0 + r) * 64 + d4 * 4];
                ka[r] = *(const float4*)&shK[ksw4(s0 + r, d4)];
            }
#pragma unroll
            for (int r = 0; r < 4; r++)
#pragma unroll
                for (int q = 0; q < 4; q++)
                    accS[r][q] += qa[r].x * ka[q].x + qa[r].y * ka[q].y + qa[r].z * ka[q].z +
                                  qa[r].w * ka[q].w;
        }
        __syncthreads();  // shS (P/Pinv) no longer needed; safe to overwrite
#pragma unroll
        for (int r = 0; r < 4; r++)
#pragma unroll
            for (int q = 0; q < 4; q++) {
                int i = i0 + r, s = s0 + q;
                shS[i * 64 + s] = (s <= i) ? ETA_C * accS[r][q] : 0.f;
            }
    }
    __syncthreads();

    // load V into shQ
    for (int idx = t; idx < 4096; idx += 256) {
        int i = idx >> 6, d = idx & 63;
        shQ[i * 64 + d] = g_qkv[(size_t)(t0 + i) * 1536 + 1024 + h * 64 + d];
    }
    __syncthreads();

    // O_intra[i][e] = sum_s S[i][s] * V[s][e]
    {
        int i0 = (t >> 4) * 4, e0 = (t & 15) * 4;
        float accO[4][4];
#pragma unroll
        for (int r = 0; r < 4; r++)
#pragma unroll
            for (int q = 0; q < 4; q++) accO[r][q] = 0.f;
        for (int s = 0; s < 64; s++) {
            float4 vv = *(const float4*)&shQ[s * 64 + e0];
            float sv[4];
#pragma unroll
            for (int r = 0; r < 4; r++) sv[r] = shS[(i0 + r) * 64 + s];
#pragma unroll
            for (int r = 0; r < 4; r++) {
                accO[r][0] += sv[r] * vv.x;
                accO[r][1] += sv[r] * vv.y;
                accO[r][2] += sv[r] * vv.z;
                accO[r][3] += sv[r] * vv.w;
            }
        }
#pragma unroll
        for (int r = 0; r < 4; r++) {
            float4 o4 = make_float4(accO[r][0], accO[r][1], accO[r][2], accO[r][3]);
            *(float4*)&g_Oin[(size_t)(t0 + i0 + r) * 512 + h * 64 + e0] = o4;
        }
    }

    // U[d][e] = sum_s Ks[s][d] * V[s][e]
    {
        int d0 = (t >> 4) * 4, e0 = (t & 15) * 4;
        float accU[4][4];
#pragma unroll
        for (int r = 0; r < 4; r++)
#pragma unroll
            for (int q = 0; q < 4; q++) accU[r][q] = 0.f;
        for (int s = 0; s < 64; s++) {
            float4 vv = *(const float4*)&shQ[s * 64 + e0];
            float kv[4];
#pragma unroll
            for (int r = 0; r < 4; r++) kv[r] = shK[ksw(s, d0 + r)];
#pragma unroll
            for (int r = 0; r < 4; r++) {
                accU[r][0] += kv[r] * vv.x;
                accU[r][1] += kv[r] * vv.y;
                accU[r][2] += kv[r] * vv.z;
                accU[r][3] += kv[r] * vv.w;
            }
        }
        size_t ub = ((size_t)bh * 32 + c) * 4096;
#pragma unroll
        for (int r = 0; r < 4; r++) {
            float4 u4 = make_float4(accU[r][0], accU[r][1], accU[r][2], accU[r][3]);
            *(float4*)&g_U[ub + (d0 + r) * 64 + e0] = u4;
        }
    }
}

// H2a: chunk-level W recurrence (32 serial steps, parallel over bh)
__global__ void heb_state_kernel() {
    int bh = blockIdx.x;
    int t = threadIdx.x;  // 256, 16 floats each
    float4 W[4];
#pragma unroll
    for (int j = 0; j < 4; j++) W[j] = make_float4(0.f, 0.f, 0.f, 0.f);
    for (int c = 0; c < 32; c++) {
        size_t off = ((size_t)bh * 32 + c) * 4096 + t * 16;
        float pl = g_Pl[bh * 32 + c];
#pragma unroll
        for (int j = 0; j < 4; j++) {
            float4 u = *(const float4*)&g_U[off + j * 4];
            *(float4*)&g_Wst[off + j * 4] = W[j];
            W[j].x = pl * (W[j].x + ETA_C * u.x);
            W[j].y = pl * (W[j].y + ETA_C * u.y);
            W[j].z = pl * (W[j].z + ETA_C * u.z);
            W[j].w = pl * (W[j].w + ETA_C * u.w);
        }
    }
}

// H2b: O = O_intra + Qs @ Wstate  (parallel over all (b,h,chunk))
__global__ __launch_bounds__(256) void heb_inter_kernel() {
    int bid = blockIdx.x;
    int c = bid & 31;
    int bh = bid >> 5;
    int h = bh & 7;
    int b = bh >> 3;
    int t0 = b * Nseq + c * 64;
    __shared__ float shQ2[4096];
    __shared__ float shW[4096];
    int t = threadIdx.x;
    size_t wb = ((size_t)bh * 32 + c) * 4096;
    for (int idx = t; idx < 4096; idx += 256) {
        int i = idx >> 6, d = idx & 63;
        shQ2[i * 64 + d] = g_Qs[(size_t)(t0 + i) * 512 + h * 64 + d];
        shW[idx] = g_Wst[wb + idx];
    }
    __syncthreads();
    int i0 = (t >> 4) * 4, e0 = (t & 15) * 4;
    float acc[4][4];
#pragma unroll
    for (int r = 0; r < 4; r++) {
        float4 o4 = *(const float4*)&g_Oin[(size_t)(t0 + i0 + r) * 512 + h * 64 + e0];
        acc[r][0] = o4.x; acc[r][1] = o4.y; acc[r][2] = o4.z; acc[r][3] = o4.w;
    }
    for (int d = 0; d < 64; d++) {
        float4 wv = *(const float4*)&shW[d * 64 + e0];
        float qv[4];
#pragma unroll
        for (int r = 0; r < 4; r++) qv[r] = shQ2[(i0 + r) * 64 + d];
#pragma unroll
        for (int r = 0; r < 4; r++) {
            acc[r][0] += qv[r] * wv.x;
            acc[r][1] += qv[r] * wv.y;
            acc[r][2] += qv[r] * wv.z;
            acc[r][3] += qv[r] * wv.w;
        }
    }
#pragma unroll
    for (int r = 0; r < 4; r++) {
        float4 o4 = make_float4(acc[r][0], acc[r][1], acc[r][2], acc[r][3]);
        *(float4*)&g_heb[(size_t)(t0 + i0 + r) * 512 + h * 64 + e0] = o4;
    }
}

// ---------------- launch ----------------
extern "C" void kernel_launch(void* const* d_in, const int* in_sizes, int n_in,
                              void* d_out, int out_size) {
    const float* x     = (const float*)d_in[0];
    const float* ln1_g = (const float*)d_in[1];
    const float* ln1_b = (const float*)d_in[2];
    const float* ln2_g = (const float*)d_in[3];
    const float* ln2_b = (const float*)d_in[4];
    const float* ln3_g = (const float*)d_in[5];
    const float* ln3_b = (const float*)d_in[6];
    const float* w_pot = (const float*)d_in[7];
    const float* b_pot = (const float*)d_in[8];
    const float* w_bk  = (const float*)d_in[9];
    const float* b_bk  = (const float*)d_in[10];
    const float* w_qkv = (const float*)d_in[11];
    const float* b_qkv = (const float*)d_in[12];
    const float* w_out = (const float*)d_in[13];
    const float* b_out = (const float*)d_in[14];
    const float* w_ff1 = (const float*)d_in[15];
    const float* b_ff1 = (const float*)d_in[16];
    const float* w_ff2 = (const float*)d_in[17];
    const float* b_ff2 = (const float*)d_in[18];
    float* out = (float*)d_out;

    float *p_xn2, *p_qkv, *p_heb, *p_x1, *p_x2, *p_xn3, *p_ff;
    cudaGetSymbolAddress((void**)&p_xn2, g_xn2);
    cudaGetSymbolAddress((void**)&p_qkv, g_qkv);
    cudaGetSymbolAddress((void**)&p_heb, g_heb);
    cudaGetSymbolAddress((void**)&p_x1, g_x1);
    cudaGetSymbolAddress((void**)&p_x2, g_x2);
    cudaGetSymbolAddress((void**)&p_xn3, g_xn3);
    cudaGetSymbolAddress((void**)&p_ff, g_ff);

    ln1_pot_kernel<<<Ttok, 256>>>(x, ln1_g, ln1_b, w_pot, b_pot);
    bk_scan_kernel<<<8, 128>>>();
    bk_res_ln2_kernel<<<Ttok, 256>>>(x, w_bk, b_bk, ln2_g, ln2_b);
    sgemm_kernel<0><<<dim3(12, 64), 256>>>(p_xn2, w_qkv, b_qkv, nullptr, p_qkv, Ttok, 1536, Ddim);
    heb_intra_kernel<<<1024, 256>>>();
    heb_state_kernel<<<32, 256>>>();
    heb_inter_kernel<<<1024, 256>>>();
    sgemm_kernel<0><<<dim3(8, 64), 256>>>(p_heb, w_out, b_out, p_x1, p_x2, Ttok, Ddim, 512);
    ln3_kernel<<<Ttok, 256>>>(ln3_g, ln3_b);
    sgemm_kernel<1><<<dim3(32, 64), 256>>>(p_xn3, w_ff1, b_ff1, nullptr, p_ff, Ttok, FFd, Ddim);
    sgemm_kernel<0><<<dim3(8, 64), 256>>>(p_ff, w_ff2, b_ff2, p_x2, out, Ttok, Ddim, FFd);
}

// round 3
// speedup vs baseline: 2.5219x; 2.5219x over previous
#include <cuda_runtime.h>
#include <stdint.h>
#include <math.h>

#define Bdim 4
#define Nseq 2048
#define Ddim 1024
#define Hh   8
#define HDd  64
#define FFd  4096
#define Ttok 8192                 // B*N
#define ETA_C 0.1f
#define DT_C  0.01f

// ---------------- scratch (static device globals; no allocations) ----------------
__device__ float g_V[Ttok];
__device__ float g_gamma[Ttok];
__device__ float g_a[Ttok * 2];
__device__ float g_bcf[Ttok * 2];
__device__ float g_x1[(size_t)Ttok * Ddim];
__device__ float g_xn2[(size_t)Ttok * Ddim];
__device__ float g_qkv[(size_t)Ttok * 1536];
__device__ float g_Qs[(size_t)Ttok * 512];
__device__ float g_Oin[(size_t)Ttok * 512];
__device__ float g_heb[(size_t)Ttok * 512];
__device__ float g_U[32 * 32 * 4096];       // [bh][chunk][d][e]
__device__ float g_Wst[32 * 32 * 4096];     // [bh][chunk][d][e]
__device__ float g_Pl[32 * 32];
__device__ float g_x2[(size_t)Ttok * Ddim];
__device__ float g_xn3[(size_t)Ttok * Ddim];
__device__ float g_ff[(size_t)Ttok * FFd];

// ---------------- helpers ----------------
__device__ __forceinline__ float blk_sum256(float v, float* sh) {
    int t = threadIdx.x;
#pragma unroll
    for (int o = 16; o > 0; o >>= 1) v += __shfl_down_sync(0xffffffffu, v, o);
    if ((t & 31) == 0) sh[t >> 5] = v;
    __syncthreads();
    if (t < 32) {
        float r = (t < 8) ? sh[t] : 0.f;
#pragma unroll
        for (int o = 4; o > 0; o >>= 1) r += __shfl_down_sync(0xffffffffu, r, o);
        if (t == 0) sh[0] = r;
    }
    __syncthreads();
    float r = sh[0];
    __syncthreads();
    return r;
}

__device__ __forceinline__ float gelu_f(float x) {
    float x3 = x * x * x;
    float u = 0.7978845608028654f * (x + 0.044715f * x3);
    return 0.5f * x * (1.f + tanhf(u));
}

// ---------------- K1: LN1 + potential projection ----------------
__global__ void ln1_pot_kernel(const float* __restrict__ x, const float* __restrict__ g1,
                               const float* __restrict__ b1, const float* __restrict__ wpot,
                               const float* __restrict__ bpot) {
    int row = blockIdx.x;
    int t = threadIdx.x;
    __shared__ float sh[8];
    const float4* xr = (const float4*)(x + (size_t)row * Ddim);
    float4 xv = xr[t];
    float s = xv.x + xv.y + xv.z + xv.w;
    float ss = xv.x * xv.x + xv.y * xv.y + xv.z * xv.z + xv.w * xv.w;
    s = blk_sum256(s, sh);
    ss = blk_sum256(ss, sh);
    float m = s * (1.f / Ddim);
    float var = ss * (1.f / Ddim) - m * m;
    float rstd = rsqrtf(var + 1e-5f);
    float xa[4] = {xv.x, xv.y, xv.z, xv.w};
    float p0 = 0.f, p1 = 0.f;
#pragma unroll
    for (int j = 0; j < 4; j++) {
        int col = t * 4 + j;
        float xn = (xa[j] - m) * rstd * g1[col] + b1[col];
        p0 += xn * wpot[col * 2];
        p1 += xn * wpot[col * 2 + 1];
    }
    p0 = blk_sum256(p0, sh);
    p1 = blk_sum256(p1, sh);
    if (t == 0) {
        g_V[row] = p0 + bpot[0];
        float z = p1 + bpot[1];
        float sp = (z > 20.f) ? z : log1pf(expf(z));
        g_gamma[row] = sp + 0.1f;
    }
}

// ---------------- K2: continued-fraction scans (fwd a, bwd b) ----------------
__global__ void bk_scan_kernel() {
    int bb = blockIdx.x >> 1;
    int dir = blockIdx.x & 1;
    __shared__ float dre[128], dii[128], ore[128], oim[128];
    int t = threadIdx.x;
    float pre = 0.f, pim = 0.f;
    float* out = dir ? g_bcf : g_a;
    for (int c = 0; c < 16; c++) {
        int j = c * 128 + t;
        int pos = dir ? (Nseq - 1 - j) : j;
        int gi = bb * Nseq + pos;
        dre[t] = g_V[gi] + 2.f;
        dii[t] = -g_gamma[gi];
        __syncthreads();
        if (t == 0) {
            for (int u = 0; u < 128; u++) {
                float ar, ai;
                if (c == 0 && u == 0) {
                    ar = dre[0]; ai = dii[0];
                } else {
                    float inv = 1.f / (pre * pre + pim * pim);
                    ar = dre[u] - pre * inv;
                    ai = dii[u] + pim * inv;
                }
                ore[u] = ar; oim[u] = ai;
                pre = ar; pim = ai;
            }
        }
        __syncthreads();
        out[gi * 2] = ore[t];
        out[gi * 2 + 1] = oim[t];
        __syncthreads();
    }
}

// ---------------- K3: BK combine + residual + LN2 ----------------
__global__ void bk_res_ln2_kernel(const float* __restrict__ x, const float* __restrict__ wbk,
                                  const float* __restrict__ bbk, const float* __restrict__ g2,
                                  const float* __restrict__ b2) {
    int row = blockIdx.x;
    int t = threadIdx.x;
    __shared__ float sh[8];
    __shared__ float f01[2];
    if (t == 0) {
        float are = g_a[row * 2], aim = g_a[row * 2 + 1];
        float bre = g_bcf[row * 2], bim = g_bcf[row * 2 + 1];
        float dr = g_V[row] + 2.f, di = -g_gamma[row];
        float nr = are + bre - dr, ni = aim + bim - di;
        float inv = 1.f / (nr * nr + ni * ni);
        f01[0] = nr * inv;
        f01[1] = -ni * inv;
    }
    __syncthreads();
    float f0 = f01[0], f1 = f01[1];
    size_t base = (size_t)row * Ddim;
    float y[4];
    float s = 0.f, ss = 0.f;
#pragma unroll
    for (int j = 0; j < 4; j++) {
        int col = t * 4 + j;
        float v = x[base + col] + f0 * wbk[col] + f1 * wbk[Ddim + col] + bbk[col];
        y[j] = v;
        s += v;
        ss += v * v;
        g_x1[base + col] = v;
    }
    s = blk_sum256(s, sh);
    ss = blk_sum256(ss, sh);
    float m = s * (1.f / Ddim);
    float var = ss * (1.f / Ddim) - m * m;
    float rstd = rsqrtf(var + 1e-5f);
#pragma unroll
    for (int j = 0; j < 4; j++) {
        int col = t * 4 + j;
        g_xn2[base + col] = (y[j] - m) * rstd * g2[col] + b2[col];
    }
}

// ---------------- LN3 ----------------
__global__ void ln3_kernel(const float* __restrict__ g3, const float* __restrict__ b3) {
    int row = blockIdx.x;
    int t = threadIdx.x;
    __shared__ float sh[8];
    size_t base = (size_t)row * Ddim;
    float4 xv = *(const float4*)&g_x2[base + t * 4];
    float s = xv.x + xv.y + xv.z + xv.w;
    float ss = xv.x * xv.x + xv.y * xv.y + xv.z * xv.z + xv.w * xv.w;
    s = blk_sum256(s, sh);
    ss = blk_sum256(ss, sh);
    float m = s * (1.f / Ddim);
    float var = ss * (1.f / Ddim) - m * m;
    float rstd = rsqrtf(var + 1e-5f);
    float xa[4] = {xv.x, xv.y, xv.z, xv.w};
#pragma unroll
    for (int j = 0; j < 4; j++) {
        int col = t * 4 + j;
        g_xn3[base + col] = (xa[j] - m) * rstd * g3[col] + b3[col];
    }
}

// ---------------- TF32 tensor-core GEMM ----------------
// 128x128 block, 8 warps (2x4), warp tile 64x32, K-step 16, cp.async double buffer.
// C[M,N] = A[M,K]@B[K,N] + bias ; EPI==1 -> gelu ; Rd -> += residual
#define AST 20            // A smem row stride (floats)
#define BST 132           // B smem row stride (floats)
#define ABUF (128 * AST)  // 2560 floats per buffer
#define BBUF (16 * BST)   // 2112 floats per buffer

__device__ __forceinline__ void cpa16(unsigned int dst, const void* src) {
    asm volatile("cp.async.ca.shared.global [%0], [%1], 16;\n" ::"r"(dst), "l"(src));
}
__device__ __forceinline__ unsigned int f2tf32(float f) {
    unsigned int u;
    asm("cvt.rna.tf32.f32 %0, %1;\n" : "=r"(u) : "f"(f));
    return u;
}

template <int EPI>
__global__ __launch_bounds__(256, 2) void tf32_gemm_kernel(const float* __restrict__ A,
                                                           const float* __restrict__ B,
                                                           const float* __restrict__ bias,
                                                           const float* __restrict__ Rd,
                                                           float* __restrict__ C, int M, int N,
                                                           int K) {
    __shared__ float As[2 * ABUF];
    __shared__ float Bs[2 * BBUF];
    int t = threadIdx.x;
    int warp = t >> 5, lane = t & 31;
    int gid = lane >> 2, tig = lane & 3;
    int m0 = blockIdx.y * 128, n0 = blockIdx.x * 128;
    int wm = (warp >> 2) * 64, wn = (warp & 3) * 32;

    float acc[4][4][4];
#pragma unroll
    for (int i = 0; i < 4; i++)
#pragma unroll
        for (int j = 0; j < 4; j++)
#pragma unroll
            for (int r = 0; r < 4; r++) acc[i][j][r] = 0.f;

    unsigned int asBase = (unsigned int)__cvta_generic_to_shared(As);
    unsigned int bsBase = (unsigned int)__cvta_generic_to_shared(Bs);
    unsigned int aDst0 = asBase + (((t >> 2) * AST + (t & 3) * 4) << 2);
    unsigned int aDst1 = aDst0 + ((64 * AST) << 2);
    unsigned int bDst0 = bsBase + (((t >> 5) * BST + (t & 31) * 4) << 2);
    unsigned int bDst1 = bDst0 + ((8 * BST) << 2);
    const float* Ag0 = A + (size_t)(m0 + (t >> 2)) * K + (t & 3) * 4;
    const float* Ag1 = Ag0 + (size_t)64 * K;
    const float* Bg0 = B + (size_t)(t >> 5) * N + n0 + (t & 31) * 4;
    const float* Bg1 = Bg0 + (size_t)8 * N;

    const int KT = K >> 4;

    // preload tile 0
    cpa16(aDst0, Ag0);
    cpa16(aDst1, Ag1);
    cpa16(bDst0, Bg0);
    cpa16(bDst1, Bg1);
    asm volatile("cp.async.commit_group;\n");

    for (int kt = 0; kt < KT; kt++) {
        if (kt + 1 < KT) {
            unsigned int ab = (unsigned int)((kt + 1) & 1) * ((unsigned int)(ABUF) << 2);
            unsigned int bb = (unsigned int)((kt + 1) & 1) * ((unsigned int)(BBUF) << 2);
            int ko = (kt + 1) << 4;
            cpa16(aDst0 + ab, Ag0 + ko);
            cpa16(aDst1 + ab, Ag1 + ko);
            cpa16(bDst0 + bb, Bg0 + (size_t)ko * N);
            cpa16(bDst1 + bb, Bg1 + (size_t)ko * N);
            asm volatile("cp.async.commit_group;\n");
            asm volatile("cp.async.wait_group 1;\n");
        } else {
            asm volatile("cp.async.wait_group 0;\n");
        }
        __syncthreads();
        const float* as = As + (kt & 1) * ABUF;
        const float* bs = Bs + (kt & 1) * BBUF;
#pragma unroll
        for (int kk = 0; kk < 16; kk += 8) {
            unsigned int af[4][4], bf[4][2];
#pragma unroll
            for (int mt = 0; mt < 4; mt++) {
                int rb = wm + mt * 16 + gid;
                af[mt][0] = f2tf32(as[rb * AST + kk + tig]);
                af[mt][1] = f2tf32(as[(rb + 8) * AST + kk + tig]);
                af[mt][2] = f2tf32(as[rb * AST + kk + tig + 4]);
                af[mt][3] = f2tf32(as[(rb + 8) * AST + kk + tig + 4]);
            }
#pragma unroll
            for (int nt = 0; nt < 4; nt++) {
                int cb = wn + nt * 8 + gid;
                bf[nt][0] = f2tf32(bs[(kk + tig) * BST + cb]);
                bf[nt][1] = f2tf32(bs[(kk + tig + 4) * BST + cb]);
            }
#pragma unroll
            for (int mt = 0; mt < 4; mt++)
#pragma unroll
                for (int nt = 0; nt < 4; nt++) {
                    asm volatile(
                        "mma.sync.aligned.m16n8k8.row.col.f32.tf32.tf32.f32 "
                        "{%0,%1,%2,%3}, {%4,%5,%6,%7}, {%8,%9}, {%0,%1,%2,%3};\n"
                        : "+f"(acc[mt][nt][0]), "+f"(acc[mt][nt][1]), "+f"(acc[mt][nt][2]),
                          "+f"(acc[mt][nt][3])
                        : "r"(af[mt][0]), "r"(af[mt][1]), "r"(af[mt][2]), "r"(af[mt][3]),
                          "r"(bf[nt][0]), "r"(bf[nt][1]));
                }
        }
        __syncthreads();
    }

    // epilogue
#pragma unroll
    for (int mt = 0; mt < 4; mt++) {
        int row = m0 + wm + mt * 16 + gid;
#pragma unroll
        for (int nt = 0; nt < 4; nt++) {
            int col = n0 + wn + nt * 8 + tig * 2;
            float b0 = bias[col], b1 = bias[col + 1];
            float v0 = acc[mt][nt][0] + b0;
            float v1 = acc[mt][nt][1] + b1;
            float v2 = acc[mt][nt][2] + b0;
            float v3 = acc[mt][nt][3] + b1;
            if (EPI == 1) {
                v0 = gelu_f(v0); v1 = gelu_f(v1); v2 = gelu_f(v2); v3 = gelu_f(v3);
            }
            size_t o0 = (size_t)row * N + col;
            size_t o2 = (size_t)(row + 8) * N + col;
            if (Rd != nullptr) {
                float2 r0 = *(const float2*)&Rd[o0];
                float2 r2 = *(const float2*)&Rd[o2];
                v0 += r0.x; v1 += r0.y; v2 += r2.x; v3 += r2.y;
            }
            *(float2*)&C[o0] = make_float2(v0, v1);
            *(float2*)&C[o2] = make_float2(v2, v3);
        }
    }
}

// ---------------- Hebbian chunked linear attention ----------------
__device__ __forceinline__ int ksw(int s, int d) {
    return s * 64 + (((((d >> 2) ^ (s & 15)) & 15) << 2) | (d & 3));
}
__device__ __forceinline__ int ksw4(int s, int d4) {
    return s * 64 + ((((d4 ^ (s & 15)) & 15) << 2));
}

__global__ __launch_bounds__(256) void heb_intra_kernel() {
    int bid = blockIdx.x;
    int c = bid & 31;
    int bh = bid >> 5;
    int h = bh & 7;
    int b = bh >> 3;
    int t0 = b * Nseq + c * 64;
    __shared__ float shQ[4096];
    __shared__ float shK[4096];
    __shared__ float shS[4096];
    int t = threadIdx.x;

    if (t < 64) shS[t] = g_gamma[t0 + t];
    __syncthreads();
    if (t == 0) {
        float cum = 0.f;
        for (int i = 0; i < 64; i++) {
            cum += shS[i];
            shS[i] = expf(-DT_C * cum);
        }
        g_Pl[bh * 32 + c] = shS[63];
    }
    __syncthreads();
    if (t < 64) shS[64 + t] = 1.f / shS[t];
    __syncthreads();

    for (int idx = t; idx < 4096; idx += 256) {
        int i = idx >> 6, d = idx & 63;
        size_t qb = (size_t)(t0 + i) * 1536 + h * 64 + d;
        float qs = g_qkv[qb] * shS[i];
        shQ[i * 64 + d] = qs;
        g_Qs[(size_t)(t0 + i) * 512 + h * 64 + d] = qs;
        shK[ksw(i, d)] = g_qkv[qb + 512] * shS[64 + i];
    }
    __syncthreads();

    {
        int i0 = (t >> 4) * 4, s0 = (t & 15) * 4;
        float accS[4][4];
#pragma unroll
        for (int r = 0; r < 4; r++)
#pragma unroll
            for (int q = 0; q < 4; q++) accS[r][q] = 0.f;
#pragma unroll
        for (int d4 = 0; d4 < 16; d4++) {
            float4 qa[4], ka[4];
#pragma unroll
            for (int r = 0; r < 4; r++) {
                qa[r] = *(const float4*)&shQ[(i0 + r) * 64 + d4 * 4];
                ka[r] = *(const float4*)&shK[ksw4(s0 + r, d4)];
            }
#pragma unroll
            for (int r = 0; r < 4; r++)
#pragma unroll
                for (int q = 0; q < 4; q++)
                    accS[r][q] += qa[r].x * ka[q].x + qa[r].y * ka[q].y + qa[r].z * ka[q].z +
                                  qa[r].w * ka[q].w;
        }
        __syncthreads();
#pragma unroll
        for (int r = 0; r < 4; r++)
#pragma unroll
            for (int q = 0; q < 4; q++) {
                int i = i0 + r, s = s0 + q;
                shS[i * 64 + s] = (s <= i) ? ETA_C * accS[r][q] : 0.f;
            }
    }
    __syncthreads();

    for (int idx = t; idx < 4096; idx += 256) {
        int i = idx >> 6, d = idx & 63;
        shQ[i * 64 + d] = g_qkv[(size_t)(t0 + i) * 1536 + 1024 + h * 64 + d];
    }
    __syncthreads();

    {
        int i0 = (t >> 4) * 4, e0 = (t & 15) * 4;
        float accO[4][4];
#pragma unroll
        for (int r = 0; r < 4; r++)
#pragma unroll
            for (int q = 0; q < 4; q++) accO[r][q] = 0.f;
        for (int s = 0; s < 64; s++) {
            float4 vv = *(const float4*)&shQ[s * 64 + e0];
            float sv[4];
#pragma unroll
            for (int r = 0; r < 4; r++) sv[r] = shS[(i0 + r) * 64 + s];
#pragma unroll
            for (int r = 0; r < 4; r++) {
                accO[r][0] += sv[r] * vv.x;
                accO[r][1] += sv[r] * vv.y;
                accO[r][2] += sv[r] * vv.z;
                accO[r][3] += sv[r] * vv.w;
            }
        }
#pragma unroll
        for (int r = 0; r < 4; r++) {
            float4 o4 = make_float4(accO[r][0], accO[r][1], accO[r][2], accO[r][3]);
            *(float4*)&g_Oin[(size_t)(t0 + i0 + r) * 512 + h * 64 + e0] = o4;
        }
    }

    {
        int d0 = (t >> 4) * 4, e0 = (t & 15) * 4;
        float accU[4][4];
#pragma unroll
        for (int r = 0; r < 4; r++)
#pragma unroll
            for (int q = 0; q < 4; q++) accU[r][q] = 0.f;
        for (int s = 0; s < 64; s++) {
            float4 vv = *(const float4*)&shQ[s * 64 + e0];
            float kv[4];
#pragma unroll
            for (int r = 0; r < 4; r++) kv[r] = shK[ksw(s, d0 + r)];
#pragma unroll
            for (int r = 0; r < 4; r++) {
                accU[r][0] += kv[r] * vv.x;
                accU[r][1] += kv[r] * vv.y;
                accU[r][2] += kv[r] * vv.z;
                accU[r][3] += kv[r] * vv.w;
            }
        }
        size_t ub = ((size_t)bh * 32 + c) * 4096;
#pragma unroll
        for (int r = 0; r < 4; r++) {
            float4 u4 = make_float4(accU[r][0], accU[r][1], accU[r][2], accU[r][3]);
            *(float4*)&g_U[ub + (d0 + r) * 64 + e0] = u4;
        }
    }
}

__global__ void heb_state_kernel() {
    int bh = blockIdx.x;
    int t = threadIdx.x;
    float4 W[4];
#pragma unroll
    for (int j = 0; j < 4; j++) W[j] = make_float4(0.f, 0.f, 0.f, 0.f);
    for (int c = 0; c < 32; c++) {
        size_t off = ((size_t)bh * 32 + c) * 4096 + t * 16;
        float pl = g_Pl[bh * 32 + c];
#pragma unroll
        for (int j = 0; j < 4; j++) {
            float4 u = *(const float4*)&g_U[off + j * 4];
            *(float4*)&g_Wst[off + j * 4] = W[j];
            W[j].x = pl * (W[j].x + ETA_C * u.x);
            W[j].y = pl * (W[j].y + ETA_C * u.y);
            W[j].z = pl * (W[j].z + ETA_C * u.z);
            W[j].w = pl * (W[j].w + ETA_C * u.w);
        }
    }
}

__global__ __launch_bounds__(256) void heb_inter_kernel() {
    int bid = blockIdx.x;
    int c = bid & 31;
    int bh = bid >> 5;
    int h = bh & 7;
    int b = bh >> 3;
    int t0 = b * Nseq + c * 64;
    __shared__ float shQ2[4096];
    __shared__ float shW[4096];
    int t = threadIdx.x;
    size_t wb = ((size_t)bh * 32 + c) * 4096;
    for (int idx = t; idx < 4096; idx += 256) {
        int i = idx >> 6, d = idx & 63;
        shQ2[i * 64 + d] = g_Qs[(size_t)(t0 + i) * 512 + h * 64 + d];
        shW[idx] = g_Wst[wb + idx];
    }
    __syncthreads();
    int i0 = (t >> 4) * 4, e0 = (t & 15) * 4;
    float acc[4][4];
#pragma unroll
    for (int r = 0; r < 4; r++) {
        float4 o4 = *(const float4*)&g_Oin[(size_t)(t0 + i0 + r) * 512 + h * 64 + e0];
        acc[r][0] = o4.x; acc[r][1] = o4.y; acc[r][2] = o4.z; acc[r][3] = o4.w;
    }
    for (int d = 0; d < 64; d++) {
        float4 wv = *(const float4*)&shW[d * 64 + e0];
        float qv[4];
#pragma unroll
        for (int r = 0; r < 4; r++) qv[r] = shQ2[(i0 + r) * 64 + d];
#pragma unroll
        for (int r = 0; r < 4; r++) {
            acc[r][0] += qv[r] * wv.x;
            acc[r][1] += qv[r] * wv.y;
            acc[r][2] += qv[r] * wv.z;
            acc[r][3] += qv[r] * wv.w;
        }
    }
#pragma unroll
    for (int r = 0; r < 4; r++) {
        float4 o4 = make_float4(acc[r][0], acc[r][1], acc[r][2], acc[r][3]);
        *(float4*)&g_heb[(size_t)(t0 + i0 + r) * 512 + h * 64 + e0] = o4;
    }
}

// ---------------- launch ----------------
extern "C" void kernel_launch(void* const* d_in, const int* in_sizes, int n_in,
                              void* d_out, int out_size) {
    const float* x     = (const float*)d_in[0];
    const float* ln1_g = (const float*)d_in[1];
    const float* ln1_b = (const float*)d_in[2];
    const float* ln2_g = (const float*)d_in[3];
    const float* ln2_b = (const float*)d_in[4];
    const float* ln3_g = (const float*)d_in[5];
    const float* ln3_b = (const float*)d_in[6];
    const float* w_pot = (const float*)d_in[7];
    const float* b_pot = (const float*)d_in[8];
    const float* w_bk  = (const float*)d_in[9];
    const float* b_bk  = (const float*)d_in[10];
    const float* w_qkv = (const float*)d_in[11];
    const float* b_qkv = (const float*)d_in[12];
    const float* w_out = (const float*)d_in[13];
    const float* b_out = (const float*)d_in[14];
    const float* w_ff1 = (const float*)d_in[15];
    const float* b_ff1 = (const float*)d_in[16];
    const float* w_ff2 = (const float*)d_in[17];
    const float* b_ff2 = (const float*)d_in[18];
    float* out = (float*)d_out;

    float *p_xn2, *p_qkv, *p_heb, *p_x1, *p_x2, *p_xn3, *p_ff;
    cudaGetSymbolAddress((void**)&p_xn2, g_xn2);
    cudaGetSymbolAddress((void**)&p_qkv, g_qkv);
    cudaGetSymbolAddress((void**)&p_heb, g_heb);
    cudaGetSymbolAddress((void**)&p_x1, g_x1);
    cudaGetSymbolAddress((void**)&p_x2, g_x2);
    cudaGetSymbolAddress((void**)&p_xn3, g_xn3);
    cudaGetSymbolAddress((void**)&p_ff, g_ff);

    ln1_pot_kernel<<<Ttok, 256>>>(x, ln1_g, ln1_b, w_pot, b_pot);
    bk_scan_kernel<<<8, 128>>>();
    bk_res_ln2_kernel<<<Ttok, 256>>>(x, w_bk, b_bk, ln2_g, ln2_b);
    tf32_gemm_kernel<0><<<dim3(12, 64), 256>>>(p_xn2, w_qkv, b_qkv, nullptr, p_qkv, Ttok, 1536, Ddim);
    heb_intra_kernel<<<1024, 256>>>();
    heb_state_kernel<<<32, 256>>>();
    heb_inter_kernel<<<1024, 256>>>();
    tf32_gemm_kernel<0><<<dim3(8, 64), 256>>>(p_heb, w_out, b_out, p_x1, p_x2, Ttok, Ddim, 512);
    ln3_kernel<<<Ttok, 256>>>(ln3_g, ln3_b);
    tf32_gemm_kernel<1><<<dim3(32, 64), 256>>>(p_xn3, w_ff1, b_ff1, nullptr, p_ff, Ttok, FFd, Ddim);
    tf32_gemm_kernel<0><<<dim3(8, 64), 256>>>(p_ff, w_ff2, b_ff2, p_x2, out, Ttok, Ddim, FFd);
}